// round 12
// baseline (speedup 1.0000x reference)
#include <cuda_runtime.h>

#define NQ 22
#define NN (1 << NQ)
#define TB 14
#define TILE (1 << TB)
#define SMEM_F2 (TILE + (TILE >> 4))
#define SMEM_BYTES (SMEM_F2 * (int)sizeof(float2))
#define INV_SQRT_N 4.8828125e-4f  /* 1/2048 exact */

// single in-place state buffer (float4-typed for 16B-aligned vector loads)
__device__ float4 g_state4[NN / 2];

__device__ __forceinline__ float2* state_ptr() {
    return reinterpret_cast<float2*>(g_state4);
}

__device__ __forceinline__ int phys(int s) { return s + (s >> 4); }

// degree-7/6 polynomial sincos; |x| <~ 0.6 -> ~1e-6 abs error.
__device__ __forceinline__ void sincos_poly(float x, float& s, float& c) {
    float x2 = x * x;
    float p = fmaf(x2, -1.9841270e-4f, 8.3333338e-3f);
    p = fmaf(x2, p, -0.16666667f);
    s = x * fmaf(x2, p, 1.0f);
    float q = fmaf(x2, -1.3888889e-3f, 4.1666668e-2f);
    q = fmaf(x2, q, -0.5f);
    c = fmaf(x2, q, 1.0f);
}

// butterfly with cos(beta) factored out: a' = a + i*t*b ; b' = b + i*t*a
__device__ __forceinline__ void bf(float2& a, float2& b, float tb) {
    float ar = a.x, ai = a.y, br = b.x, bi = b.y;
    a.x = fmaf(-tb, bi, ar);
    a.y = fmaf( tb, br, ai);
    b.x = fmaf(-tb, ai, br);
    b.y = fmaf( tb, ar, bi);
}

// 4-bit butterfly over register index j (bits 0..3 of j)
__device__ __forceinline__ void bfly4(float2 r[16], float tb) {
#pragma unroll
    for (int j = 0; j < 16; j += 2) bf(r[j], r[j + 1], tb);
#pragma unroll
    for (int g = 0; g < 16; g += 4) {
        bf(r[g + 0], r[g + 2], tb);
        bf(r[g + 1], r[g + 3], tb);
    }
#pragma unroll
    for (int g = 0; g < 16; g += 8) {
#pragma unroll
        for (int u = 0; u < 4; u++) bf(r[g + u], r[g + u + 4], tb);
    }
#pragma unroll
    for (int u = 0; u < 8; u++) bf(r[u], r[u + 8], tb);
}

// K1: initialize state = (1/sqrt(N)) * exp(i*gamma[0]*h), then layer-1
// butterflies on bits 0..13 within a contiguous 2^14 tile. Writes state.
// Block 0 thread 0 also zeroes the output accumulator (consumed only by K3).
__global__ void __launch_bounds__(1024, 1)
k1(const float* __restrict__ h, const float* __restrict__ gam,
   const float* __restrict__ bet, float* __restrict__ out) {
    extern __shared__ float2 sm[];
    float2* st = state_ptr();
    const int t = threadIdx.x;
    const unsigned base = (unsigned)blockIdx.x << TB;
    const float tb = tanf(bet[0]);
    float2 r[16];

    if (blockIdx.x == 0 && t == 0) *out = 0.0f;

    // stage 1: bits 0..3 (contiguous 16 elements per thread)
    {
        const float g = gam[0];
        const float4* h4 = reinterpret_cast<const float4*>(h + base + t * 16);
#pragma unroll
        for (int q = 0; q < 4; q++) {
            float4 hv = h4[q];
            float xs[4] = {hv.x, hv.y, hv.z, hv.w};
#pragma unroll
            for (int u = 0; u < 4; u++) {
                float sn, cs;
                sincos_poly(g * xs[u], sn, cs);
                r[q * 4 + u] = make_float2(cs * INV_SQRT_N, sn * INV_SQRT_N);
            }
        }
    }
    bfly4(r, tb);
#pragma unroll
    for (int j = 0; j < 16; j++) sm[phys(t * 16 + j)] = r[j];
    __syncthreads();

    // stage 2: bits 4..7
    {
        const int lo = t & 15, hi = (t >> 4) << 8;
#pragma unroll
        for (int j = 0; j < 16; j++) r[j] = sm[phys(lo | (j << 4) | hi)];
        bfly4(r, tb);
#pragma unroll
        for (int j = 0; j < 16; j++) sm[phys(lo | (j << 4) | hi)] = r[j];
    }
    __syncthreads();

    // stage 3: bits 8..11
    {
        const int lo = t & 255, hi = (t >> 8) << 12;
#pragma unroll
        for (int j = 0; j < 16; j++) r[j] = sm[phys(lo | (j << 8) | hi)];
        bfly4(r, tb);
#pragma unroll
        for (int j = 0; j < 16; j++) sm[phys(lo | (j << 8) | hi)] = r[j];
    }
    __syncthreads();

    // stage 4: bits 12..13 (j bits 0..1 active; j bits 2..3 passive = bits 10..11)
    {
#pragma unroll
        for (int j = 0; j < 16; j++)
            r[j] = sm[phys(t | ((j & 3) << 12) | ((j >> 2) << 10))];
#pragma unroll
        for (int g = 0; g < 16; g += 4) {
            bf(r[g + 0], r[g + 1], tb);
            bf(r[g + 2], r[g + 3], tb);
            bf(r[g + 0], r[g + 2], tb);
            bf(r[g + 1], r[g + 3], tb);
        }
#pragma unroll
        for (int j = 0; j < 16; j++)
            st[base + (unsigned)(t | ((j & 3) << 12) | ((j >> 2) << 10))] = r[j];
    }
}

// K2 (fused): tile = 256 hi-combos (bits 14..21) x 64 consecutive low; block = bits 6..13.
//   layer-1 bfly bits 14..17 -> smem transpose -> layer-1 bfly bits 18..21
//   -> exp(i*gamma[1]*h) phase -> layer-2 bfly bits 18..21 (same orientation)
//   -> smem transpose -> layer-2 bfly bits 14..17 -> write state.
__global__ void __launch_bounds__(1024, 1)
k2(const float* __restrict__ h, const float* __restrict__ gam,
   const float* __restrict__ bet) {
    extern __shared__ float2 sm[];
    float2* st = state_ptr();
    const int t = threadIdx.x;
    const unsigned mid = blockIdx.x;  // bits 6..13
    const float tb1 = tanf(bet[0]);
    const float tb2 = tanf(bet[1]);
    const int l6 = t & 63;
    const int th = t >> 6;  // 4 bits
    float2 r[16];

    // stage 1: j = bits 14..17, th = bits 18..21  (layer-1)
#pragma unroll
    for (int j = 0; j < 16; j++) {
        unsigned x = ((unsigned)((th << 4) | j) << TB) | (mid << 6) | (unsigned)l6;
        r[j] = st[x];
    }
    bfly4(r, tb1);
#pragma unroll
    for (int j = 0; j < 16; j++) sm[phys((th << 10) | (j << 6) | l6)] = r[j];
    __syncthreads();

    // stage 2: j = bits 18..21, th = bits 14..17
#pragma unroll
    for (int j = 0; j < 16; j++) r[j] = sm[phys((j << 10) | (th << 6) | l6)];
    bfly4(r, tb1);  // layer-1 bits 18..21 done

    // gamma[1] phase (elementwise)
    {
        const float g = gam[1];
#pragma unroll
        for (int j = 0; j < 16; j++) {
            unsigned x = ((unsigned)((j << 4) | th) << TB) | (mid << 6) | (unsigned)l6;
            float sn, cs;
            sincos_poly(g * h[x], sn, cs);
            float2 a = r[j];
            r[j] = make_float2(fmaf(a.x, cs, -a.y * sn), fmaf(a.x, sn, a.y * cs));
        }
    }

    bfly4(r, tb2);  // layer-2 bits 18..21 (registers already oriented)
    __syncthreads();  // everyone done reading stage-1 smem
#pragma unroll
    for (int j = 0; j < 16; j++) sm[phys((j << 10) | (th << 6) | l6)] = r[j];
    __syncthreads();

    // stage 3: back to j = bits 14..17, th = bits 18..21  (layer-2)
#pragma unroll
    for (int j = 0; j < 16; j++) r[j] = sm[phys((th << 10) | (j << 6) | l6)];
    bfly4(r, tb2);
#pragma unroll
    for (int j = 0; j < 16; j++) {
        unsigned x = ((unsigned)((th << 4) | j) << TB) | (mid << 6) | (unsigned)l6;
        st[x] = r[j];
    }
}

// K3 (fused): layer-2 butterflies on bits 0..13 in contiguous tiles, then
// sum(|c|^2 * hS) reduced straight from registers (no state writeback).
__global__ void __launch_bounds__(1024, 1)
k3(const float* __restrict__ hS, const float* __restrict__ bet,
   float* __restrict__ out) {
    extern __shared__ float2 sm[];
    float2* st = state_ptr();
    const int t = threadIdx.x;
    const unsigned base = (unsigned)blockIdx.x << TB;
    const float tb = tanf(bet[1]);
    float2 r[16];

    // stage 1: bits 0..3
    {
        const float4* c4 = &g_state4[(base >> 1) + t * 8];
#pragma unroll
        for (int q = 0; q < 8; q++) {
            float4 v = c4[q];
            r[2 * q + 0] = make_float2(v.x, v.y);
            r[2 * q + 1] = make_float2(v.z, v.w);
        }
    }
    bfly4(r, tb);
#pragma unroll
    for (int j = 0; j < 16; j++) sm[phys(t * 16 + j)] = r[j];
    __syncthreads();

    // stage 2: bits 4..7
    {
        const int lo = t & 15, hi = (t >> 4) << 8;
#pragma unroll
        for (int j = 0; j < 16; j++) r[j] = sm[phys(lo | (j << 4) | hi)];
        bfly4(r, tb);
#pragma unroll
        for (int j = 0; j < 16; j++) sm[phys(lo | (j << 4) | hi)] = r[j];
    }
    __syncthreads();

    // stage 3: bits 8..11
    {
        const int lo = t & 255, hi = (t >> 8) << 12;
#pragma unroll
        for (int j = 0; j < 16; j++) r[j] = sm[phys(lo | (j << 8) | hi)];
        bfly4(r, tb);
#pragma unroll
        for (int j = 0; j < 16; j++) sm[phys(lo | (j << 8) | hi)] = r[j];
    }
    __syncthreads();

    // stage 4: bits 12..13, then reduce |c|^2 * hS from registers
    float acc = 0.0f;
    {
#pragma unroll
        for (int j = 0; j < 16; j++)
            r[j] = sm[phys(t | ((j & 3) << 12) | ((j >> 2) << 10))];
#pragma unroll
        for (int g = 0; g < 16; g += 4) {
            bf(r[g + 0], r[g + 1], tb);
            bf(r[g + 2], r[g + 3], tb);
            bf(r[g + 0], r[g + 2], tb);
            bf(r[g + 1], r[g + 3], tb);
        }
#pragma unroll
        for (int j = 0; j < 16; j++) {
            unsigned x = base + (unsigned)(t | ((j & 3) << 12) | ((j >> 2) << 10));
            float2 a = r[j];
            acc = fmaf(fmaf(a.x, a.x, a.y * a.y), hS[x], acc);
        }
    }
#pragma unroll
    for (int o = 16; o > 0; o >>= 1) acc += __shfl_xor_sync(0xffffffffu, acc, o);
    __syncthreads();  // done with butterfly smem; reuse for block reduction
    float* red = reinterpret_cast<float*>(sm);
    if ((t & 31) == 0) red[t >> 5] = acc;
    __syncthreads();
    if (t < 32) {
        float v = red[t];
#pragma unroll
        for (int o = 16; o > 0; o >>= 1) v += __shfl_xor_sync(0xffffffffu, v, o);
        if (t == 0) {
            // factored cos(beta) per bit: amplitude cb1^22*cb2^22 -> probability (cb1*cb2)^44
            float cb = cosf(bet[0]) * cosf(bet[1]);
            atomicAdd(out, v * powf(cb, 44.0f));
        }
    }
}

extern "C" void kernel_launch(void* const* d_in, const int* in_sizes, int n_in,
                              void* d_out, int out_size) {
    const float* h   = (const float*)d_in[0];
    const float* hS  = (const float*)d_in[1];
    const float* gam = (const float*)d_in[2];
    const float* bet = (const float*)d_in[3];
    float* out = (float*)d_out;

    cudaFuncSetAttribute(k1, cudaFuncAttributeMaxDynamicSharedMemorySize, SMEM_BYTES);
    cudaFuncSetAttribute(k2, cudaFuncAttributeMaxDynamicSharedMemorySize, SMEM_BYTES);
    cudaFuncSetAttribute(k3, cudaFuncAttributeMaxDynamicSharedMemorySize, SMEM_BYTES);

    const int blocks = NN / TILE;  // 256

    k1<<<blocks, 1024, SMEM_BYTES>>>(h, gam, bet, out);
    k2<<<blocks, 1024, SMEM_BYTES>>>(h, gam, bet);
    k3<<<blocks, 1024, SMEM_BYTES>>>(hS, bet, out);
}

// round 15
// speedup vs baseline: 1.5433x; 1.5433x over previous
#include <cuda_runtime.h>

#define NQ 22
#define NN (1 << NQ)
#define TBK 13
#define TILE (1 << TBK)                 /* 8192 float2 per tile */
#define SMEM_F2 (TILE + (TILE >> 4))    /* 8704 float2, +s>>4 pad */
#define SMEM_BYTES (SMEM_F2 * (int)sizeof(float2))  /* 69632 B -> 2 CTAs/SM */
#define INV_SQRT_N 4.8828125e-4f        /* 1/2048 exact */

// single in-place state buffer (float4-typed for 16B-aligned vector loads)
__device__ float4 g_state4[NN / 2];

__device__ __forceinline__ float2* state_ptr() {
    return reinterpret_cast<float2*>(g_state4);
}

__device__ __forceinline__ int phys(int s) { return s + (s >> 4); }

// degree-7/6 polynomial sincos; |x| <~ 0.6 -> ~1e-6 abs error.
__device__ __forceinline__ void sincos_poly(float x, float& s, float& c) {
    float x2 = x * x;
    float p = fmaf(x2, -1.9841270e-4f, 8.3333338e-3f);
    p = fmaf(x2, p, -0.16666667f);
    s = x * fmaf(x2, p, 1.0f);
    float q = fmaf(x2, -1.3888889e-3f, 4.1666668e-2f);
    q = fmaf(x2, q, -0.5f);
    c = fmaf(x2, q, 1.0f);
}

// butterfly with cos(beta) factored out: a' = a + i*t*b ; b' = b + i*t*a
__device__ __forceinline__ void bf(float2& a, float2& b, float tb) {
    float ar = a.x, ai = a.y, br = b.x, bi = b.y;
    a.x = fmaf(-tb, bi, ar);
    a.y = fmaf( tb, br, ai);
    b.x = fmaf(-tb, ai, br);
    b.y = fmaf( tb, ar, bi);
}

// 3-bit butterfly over register index j (bits 0..2 of j), 8 float2 regs
__device__ __forceinline__ void bfly3(float2 r[8], float tb) {
    bf(r[0], r[1], tb); bf(r[2], r[3], tb); bf(r[4], r[5], tb); bf(r[6], r[7], tb);
    bf(r[0], r[2], tb); bf(r[1], r[3], tb); bf(r[4], r[6], tb); bf(r[5], r[7], tb);
    bf(r[0], r[4], tb); bf(r[1], r[5], tb); bf(r[2], r[6], tb); bf(r[3], r[7], tb);
}

// K1: init state = (1/sqrt(N)) * exp(i*gamma[0]*h), layer-1 butterflies on
// bits 0..12 within a contiguous 2^13 tile. 1024 thr, radix-8, 2 CTAs/SM.
__global__ void __launch_bounds__(1024, 2)
k1(const float* __restrict__ h, const float* __restrict__ gam,
   const float* __restrict__ bet, float* __restrict__ out) {
    extern __shared__ float2 sm[];
    float2* st = state_ptr();
    const int t = threadIdx.x;
    const unsigned base = (unsigned)blockIdx.x << TBK;
    const float tb = tanf(bet[0]);
    float2 r[8];

    if (blockIdx.x == 0 && t == 0) *out = 0.0f;

    // stage 1: bits 0..2 (8 contiguous elements per thread)
    {
        const float g = gam[0];
        const float4* h4 = reinterpret_cast<const float4*>(h + base + t * 8);
#pragma unroll
        for (int q = 0; q < 2; q++) {
            float4 hv = h4[q];
            float xs[4] = {hv.x, hv.y, hv.z, hv.w};
#pragma unroll
            for (int u = 0; u < 4; u++) {
                float sn, cs;
                sincos_poly(g * xs[u], sn, cs);
                r[q * 4 + u] = make_float2(cs * INV_SQRT_N, sn * INV_SQRT_N);
            }
        }
    }
    bfly3(r, tb);
#pragma unroll
    for (int j = 0; j < 8; j++) sm[phys(t * 8 + j)] = r[j];
    __syncthreads();

    // stage 2: bits 3..5
    {
        const int lo = t & 7, hi = (t >> 3) << 6;
#pragma unroll
        for (int j = 0; j < 8; j++) r[j] = sm[phys(lo | (j << 3) | hi)];
        bfly3(r, tb);
#pragma unroll
        for (int j = 0; j < 8; j++) sm[phys(lo | (j << 3) | hi)] = r[j];
    }
    __syncthreads();

    // stage 3: bits 6..8
    {
        const int lo = t & 63, hi = (t >> 6) << 9;
#pragma unroll
        for (int j = 0; j < 8; j++) r[j] = sm[phys(lo | (j << 6) | hi)];
        bfly3(r, tb);
#pragma unroll
        for (int j = 0; j < 8; j++) sm[phys(lo | (j << 6) | hi)] = r[j];
    }
    __syncthreads();

    // stage 4: bits 9..11
    {
        const int lo = t & 511, hi = (t >> 9) << 12;
#pragma unroll
        for (int j = 0; j < 8; j++) r[j] = sm[phys(lo | (j << 9) | hi)];
        bfly3(r, tb);
#pragma unroll
        for (int j = 0; j < 8; j++) sm[phys(lo | (j << 9) | hi)] = r[j];
    }
    __syncthreads();

    // stage 5: bit 12 (j bit 0 active; j bits 1..2 passive = bits 10..11)
    {
#pragma unroll
        for (int j = 0; j < 8; j++)
            r[j] = sm[phys(t | ((j & 1) << 12) | ((j >> 1) << 10))];
        bf(r[0], r[1], tb); bf(r[2], r[3], tb);
        bf(r[4], r[5], tb); bf(r[6], r[7], tb);
#pragma unroll
        for (int j = 0; j < 8; j++)
            st[base + (unsigned)(t | ((j & 1) << 12) | ((j >> 1) << 10))] = r[j];
    }
}

// K2 (fused): bits 13..21 (9 bits). Tile = 512 hi-combos x 16 consecutive low.
// Block = bits 4..12. Layer-1 A(13..15) B(16..18) C(19..21) -> phase(gamma[1])
// -> layer-2 C'(19..21, same orientation) B' A' -> write state.
__global__ void __launch_bounds__(1024, 2)
k2(const float* __restrict__ h, const float* __restrict__ gam,
   const float* __restrict__ bet) {
    extern __shared__ float2 sm[];
    float2* st = state_ptr();
    const int t = threadIdx.x;
    const unsigned mid = blockIdx.x;   // bits 4..12
    const float tb1 = tanf(bet[0]);
    const float tb2 = tanf(bet[1]);
    const int l4 = t & 15;
    const int th = t >> 4;             // 6 bits
    float2 r[8];

    // stage A: j = h9 bits 0..2 (global 13..15), th = h9 bits 3..8
#pragma unroll
    for (int j = 0; j < 8; j++) {
        unsigned x = ((unsigned)((th << 3) | j) << TBK) | (mid << 4) | (unsigned)l4;
        r[j] = st[x];
    }
    bfly3(r, tb1);
#pragma unroll
    for (int j = 0; j < 8; j++) sm[phys((th << 7) | (j << 4) | l4)] = r[j];
    __syncthreads();

    // stage B: j = h9 bits 3..5; p0 = th&7 (h9 bits 0..2), p2 = th>>3 (h9 bits 6..8)
    {
        const int p0 = th & 7, p2 = th >> 3;
#pragma unroll
        for (int j = 0; j < 8; j++)
            r[j] = sm[phys((((p2 << 6) | (j << 3) | p0) << 4) | l4)];
        bfly3(r, tb1);
#pragma unroll
        for (int j = 0; j < 8; j++)
            sm[phys((((p2 << 6) | (j << 3) | p0) << 4) | l4)] = r[j];
    }
    __syncthreads();

    // stage C: j = h9 bits 6..8; th = h9 bits 0..5. Then gamma[1] phase,
    // then layer-2 on the same bits (registers already oriented).
#pragma unroll
    for (int j = 0; j < 8; j++) r[j] = sm[phys(((j << 6) | th) << 4 | l4)];
    bfly3(r, tb1);
    {
        const float g = gam[1];
#pragma unroll
        for (int j = 0; j < 8; j++) {
            unsigned x = ((unsigned)((j << 6) | th) << TBK) | (mid << 4) | (unsigned)l4;
            float sn, cs;
            sincos_poly(g * h[x], sn, cs);
            float2 a = r[j];
            r[j] = make_float2(fmaf(a.x, cs, -a.y * sn), fmaf(a.x, sn, a.y * cs));
        }
    }
    bfly3(r, tb2);
#pragma unroll
    for (int j = 0; j < 8; j++) sm[phys(((j << 6) | th) << 4 | l4)] = r[j];
    __syncthreads();

    // stage B': layer-2 bits 16..18
    {
        const int p0 = th & 7, p2 = th >> 3;
#pragma unroll
        for (int j = 0; j < 8; j++)
            r[j] = sm[phys((((p2 << 6) | (j << 3) | p0) << 4) | l4)];
        bfly3(r, tb2);
#pragma unroll
        for (int j = 0; j < 8; j++)
            sm[phys((((p2 << 6) | (j << 3) | p0) << 4) | l4)] = r[j];
    }
    __syncthreads();

    // stage A': layer-2 bits 13..15, write state
#pragma unroll
    for (int j = 0; j < 8; j++) r[j] = sm[phys((th << 7) | (j << 4) | l4)];
    bfly3(r, tb2);
#pragma unroll
    for (int j = 0; j < 8; j++) {
        unsigned x = ((unsigned)((th << 3) | j) << TBK) | (mid << 4) | (unsigned)l4;
        st[x] = r[j];
    }
}

// K3 (fused): layer-2 butterflies on bits 0..12, then sum(|c|^2 * hS)
// reduced straight from registers (no state writeback).
__global__ void __launch_bounds__(1024, 2)
k3(const float* __restrict__ hS, const float* __restrict__ bet,
   float* __restrict__ out) {
    extern __shared__ float2 sm[];
    const int t = threadIdx.x;
    const unsigned base = (unsigned)blockIdx.x << TBK;
    const float tb = tanf(bet[1]);
    float2 r[8];

    // stage 1: bits 0..2 (8 contiguous per thread, 4x float4 loads)
    {
        const float4* c4 = &g_state4[(base >> 1) + t * 4];
#pragma unroll
        for (int q = 0; q < 4; q++) {
            float4 v = c4[q];
            r[2 * q + 0] = make_float2(v.x, v.y);
            r[2 * q + 1] = make_float2(v.z, v.w);
        }
    }
    bfly3(r, tb);
#pragma unroll
    for (int j = 0; j < 8; j++) sm[phys(t * 8 + j)] = r[j];
    __syncthreads();

    // stage 2: bits 3..5
    {
        const int lo = t & 7, hi = (t >> 3) << 6;
#pragma unroll
        for (int j = 0; j < 8; j++) r[j] = sm[phys(lo | (j << 3) | hi)];
        bfly3(r, tb);
#pragma unroll
        for (int j = 0; j < 8; j++) sm[phys(lo | (j << 3) | hi)] = r[j];
    }
    __syncthreads();

    // stage 3: bits 6..8
    {
        const int lo = t & 63, hi = (t >> 6) << 9;
#pragma unroll
        for (int j = 0; j < 8; j++) r[j] = sm[phys(lo | (j << 6) | hi)];
        bfly3(r, tb);
#pragma unroll
        for (int j = 0; j < 8; j++) sm[phys(lo | (j << 6) | hi)] = r[j];
    }
    __syncthreads();

    // stage 4: bits 9..11
    {
        const int lo = t & 511, hi = (t >> 9) << 12;
#pragma unroll
        for (int j = 0; j < 8; j++) r[j] = sm[phys(lo | (j << 9) | hi)];
        bfly3(r, tb);
#pragma unroll
        for (int j = 0; j < 8; j++) sm[phys(lo | (j << 9) | hi)] = r[j];
    }
    __syncthreads();

    // stage 5: bit 12, then reduce |c|^2 * hS from registers
    float acc = 0.0f;
    {
#pragma unroll
        for (int j = 0; j < 8; j++)
            r[j] = sm[phys(t | ((j & 1) << 12) | ((j >> 1) << 10))];
        bf(r[0], r[1], tb); bf(r[2], r[3], tb);
        bf(r[4], r[5], tb); bf(r[6], r[7], tb);
#pragma unroll
        for (int j = 0; j < 8; j++) {
            unsigned x = base + (unsigned)(t | ((j & 1) << 12) | ((j >> 1) << 10));
            float2 a = r[j];
            acc = fmaf(fmaf(a.x, a.x, a.y * a.y), hS[x], acc);
        }
    }
#pragma unroll
    for (int o = 16; o > 0; o >>= 1) acc += __shfl_xor_sync(0xffffffffu, acc, o);
    __syncthreads();  // done with butterfly smem; reuse for block reduction
    float* red = reinterpret_cast<float*>(sm);
    if ((t & 31) == 0) red[t >> 5] = acc;
    __syncthreads();
    if (t < 32) {
        float v = red[t];
#pragma unroll
        for (int o = 16; o > 0; o >>= 1) v += __shfl_xor_sync(0xffffffffu, v, o);
        if (t == 0) {
            // factored cos(beta) per bit: amplitude cb1^22*cb2^22 -> probability (cb1*cb2)^44
            float cb = cosf(bet[0]) * cosf(bet[1]);
            atomicAdd(out, v * powf(cb, 44.0f));
        }
    }
}

extern "C" void kernel_launch(void* const* d_in, const int* in_sizes, int n_in,
                              void* d_out, int out_size) {
    const float* h   = (const float*)d_in[0];
    const float* hS  = (const float*)d_in[1];
    const float* gam = (const float*)d_in[2];
    const float* bet = (const float*)d_in[3];
    float* out = (float*)d_out;

    cudaFuncSetAttribute(k1, cudaFuncAttributeMaxDynamicSharedMemorySize, SMEM_BYTES);
    cudaFuncSetAttribute(k2, cudaFuncAttributeMaxDynamicSharedMemorySize, SMEM_BYTES);
    cudaFuncSetAttribute(k3, cudaFuncAttributeMaxDynamicSharedMemorySize, SMEM_BYTES);

    const int blocks = NN / TILE;  // 512

    k1<<<blocks, 1024, SMEM_BYTES>>>(h, gam, bet, out);
    k2<<<blocks, 1024, SMEM_BYTES>>>(h, gam, bet);
    k3<<<blocks, 1024, SMEM_BYTES>>>(hS, bet, out);
}